// round 1
// baseline (speedup 1.0000x reference)
#include <cuda_runtime.h>
#include <math.h>

// Problem constants
#define T_STEPS 2048
#define B_SZ 16
#define H_SZ 1024
#define I_SZ 1024
#define G_CTAS 128      // persistent grid for recurrence (<=148 SMs -> all co-resident)

// ---------------- device scratch (static, no allocation) ----------------
__device__ float    g_Wr[H_SZ * H_SZ];      // r[h] * W_hn[h][k], diag zeroed
__device__ float    g_z[H_SZ];              // sigmoid(bias_z)
__device__ float    g_h[2][H_SZ * B_SZ];    // double-buffered h, layout [k][b]
__device__ unsigned g_bar;                  // grid barrier counter (reset each launch)

// ---------------- prep: fold r & diag into W, init h0, reset barrier ----------------
__global__ void __launch_bounds__(256) prep_kernel(
    const float* __restrict__ Whh, const float* __restrict__ brf,
    const float* __restrict__ bz,  const float* __restrict__ h0)
{
    int blk = blockIdx.x;
    if (blk < H_SZ) {
        int row = blk;
        float r = 1.0f / (1.0f + expf(-brf[row]));
        const float* src = Whh + (size_t)(2 * H_SZ + row) * H_SZ;
        for (int k = threadIdx.x; k < H_SZ; k += 256)
            g_Wr[row * H_SZ + k] = (k == row) ? 0.0f : r * src[k];
        if (threadIdx.x == 0)
            g_z[row] = 1.0f / (1.0f + expf(-bz[row]));
    } else {
        // h0: input layout [b][h]  ->  g_h[0] layout [k][b]
        for (int i = threadIdx.x; i < H_SZ * B_SZ; i += 256) {
            int k = i >> 4, b = i & 15;
            g_h[0][i] = h0[(size_t)b * H_SZ + k];
        }
        if (threadIdx.x == 0) g_bar = 0u;
    }
}

// ---------------- GEMM: pre = x @ W_in^T + bias_n  (written into y region) ----------------
// M = T*B = 32768, N = H = 1024, K = I = 1024. A and B both K-contiguous (NT gemm).
// 128x128 tile, BK=8, 256 threads, 8x8 per thread.
__global__ void __launch_bounds__(256) gemm_pre_kernel(
    const float* __restrict__ X, const float* __restrict__ Wih,
    const float* __restrict__ bn, float* __restrict__ out)
{
    __shared__ float As[8][128];
    __shared__ float Bs[8][128];
    const float* Wn = Wih + (size_t)2 * H_SZ * I_SZ;

    int m0 = blockIdx.y * 128;
    int n0 = blockIdx.x * 128;
    int t  = threadIdx.x;
    int ty = t >> 4, tx = t & 15;
    int lrow = t >> 1;
    int lk   = (t & 1) * 4;

    float acc[8][8];
#pragma unroll
    for (int i = 0; i < 8; i++)
#pragma unroll
        for (int j = 0; j < 8; j++) acc[i][j] = 0.0f;

    const float* Aptr = X  + (size_t)(m0 + lrow) * I_SZ + lk;
    const float* Bptr = Wn + (size_t)(n0 + lrow) * I_SZ + lk;

    for (int k0 = 0; k0 < I_SZ; k0 += 8) {
        float4 a = *(const float4*)(Aptr + k0);
        float4 b = *(const float4*)(Bptr + k0);
        As[lk + 0][lrow] = a.x; As[lk + 1][lrow] = a.y;
        As[lk + 2][lrow] = a.z; As[lk + 3][lrow] = a.w;
        Bs[lk + 0][lrow] = b.x; Bs[lk + 1][lrow] = b.y;
        Bs[lk + 2][lrow] = b.z; Bs[lk + 3][lrow] = b.w;
        __syncthreads();
#pragma unroll
        for (int kk = 0; kk < 8; kk++) {
            float4 a0 = *(const float4*)&As[kk][ty * 8];
            float4 a1 = *(const float4*)&As[kk][ty * 8 + 4];
            float4 b0 = *(const float4*)&Bs[kk][tx * 8];
            float4 b1 = *(const float4*)&Bs[kk][tx * 8 + 4];
            float ra[8] = {a0.x, a0.y, a0.z, a0.w, a1.x, a1.y, a1.z, a1.w};
            float rb[8] = {b0.x, b0.y, b0.z, b0.w, b1.x, b1.y, b1.z, b1.w};
#pragma unroll
            for (int i = 0; i < 8; i++)
#pragma unroll
                for (int j = 0; j < 8; j++)
                    acc[i][j] = fmaf(ra[i], rb[j], acc[i][j]);
        }
        __syncthreads();
    }

    float bj[8];
#pragma unroll
    for (int j = 0; j < 8; j++) bj[j] = bn[n0 + tx * 8 + j];

#pragma unroll
    for (int i = 0; i < 8; i++) {
        size_t o = (size_t)(m0 + ty * 8 + i) * H_SZ + n0 + tx * 8;
        float4 o0, o1;
        o0.x = acc[i][0] + bj[0]; o0.y = acc[i][1] + bj[1];
        o0.z = acc[i][2] + bj[2]; o0.w = acc[i][3] + bj[3];
        o1.x = acc[i][4] + bj[4]; o1.y = acc[i][5] + bj[5];
        o1.z = acc[i][6] + bj[6]; o1.w = acc[i][7] + bj[7];
        *(float4*)(out + o)     = o0;
        *(float4*)(out + o + 4) = o1;
    }
}

// ---------------- persistent recurrence kernel ----------------
// 128 CTAs x 256 threads. CTA c owns rows [c*8, c*8+8).
// SMEM: W_s [2][1024][4] (rg,k,row-in-group) 32KB ; h_s [4][1024][4] (bg,k,b-in-group) 64KB.
// Warp w: rg = w&1 (rows rg*4..+3), bg = w>>1 (batches bg*4..+3); lane = K segment.
__global__ void __launch_bounds__(256) recur_kernel(
    float* __restrict__ yio, float* __restrict__ hn)
{
    extern __shared__ float smem[];
    float* W_s = smem;          // 8192 floats
    float* h_s = smem + 8192;   // 16384 floats

    int c    = blockIdx.x;
    int tid  = threadIdx.x;
    int warp = tid >> 5, lane = tid & 31;
    int rg = warp & 1, bg = warp >> 1;

    // one-time load of W slice into SMEM (transposed to [rg][k][r])
    for (int i = tid; i < 2048; i += 256) {
        int r  = i >> 8;     // 0..7
        int kq = i & 255;    // float4 index over k
        float4 w = *(const float4*)(g_Wr + (size_t)(c * 8 + r) * H_SZ + kq * 4);
        int rgL = r >> 2, rL = r & 3;
        W_s[rgL * 4096 + (kq * 4 + 0) * 4 + rL] = w.x;
        W_s[rgL * 4096 + (kq * 4 + 1) * 4 + rL] = w.y;
        W_s[rgL * 4096 + (kq * 4 + 2) * 4 + rL] = w.z;
        W_s[rgL * 4096 + (kq * 4 + 3) * 4 + rL] = w.w;
    }
    __syncthreads();

    unsigned target = 0;
    for (int t = 0; t < T_STEPS; ++t) {
        // reload h (L2-coherent reads, bypass L1)
        const float4* hp = (const float4*)(g_h[t & 1]);
        for (int i = tid; i < 4096; i += 256) {
            float4 hv = __ldcg(hp + i);      // i = k*4 + bgrp
            int k = i >> 2, b4 = i & 3;
            *(float4*)&h_s[b4 * 4096 + k * 4] = hv;
        }
        __syncthreads();

        float acc[4][4];
#pragma unroll
        for (int i = 0; i < 4; i++)
#pragma unroll
            for (int j = 0; j < 4; j++) acc[i][j] = 0.0f;

#pragma unroll
        for (int it = 0; it < 32; ++it) {
            int k = lane + (it << 5);
            float4 w  = *(const float4*)&W_s[rg * 4096 + k * 4];
            float4 hv = *(const float4*)&h_s[bg * 4096 + k * 4];
            float wa[4] = {w.x, w.y, w.z, w.w};
            float ha[4] = {hv.x, hv.y, hv.z, hv.w};
#pragma unroll
            for (int i = 0; i < 4; i++)
#pragma unroll
                for (int j = 0; j < 4; j++)
                    acc[i][j] = fmaf(wa[i], ha[j], acc[i][j]);
        }

        // butterfly reduce across 32 K-segments (all lanes end with full sums)
#pragma unroll
        for (int off = 16; off > 0; off >>= 1) {
#pragma unroll
            for (int i = 0; i < 4; i++)
#pragma unroll
                for (int j = 0; j < 4; j++)
                    acc[i][j] += __shfl_xor_sync(0xffffffffu, acc[i][j], off);
        }

        if (lane < 16) {
            float dot = acc[0][0];
#pragma unroll
            for (int ii = 0; ii < 4; ii++)
#pragma unroll
                for (int jj = 0; jj < 4; jj++)
                    if (lane == ii * 4 + jj) dot = acc[ii][jj];
            int i = lane >> 2, j = lane & 3;
            int row = c * 8 + rg * 4 + i;
            int b   = bg * 4 + j;
            float hold = h_s[bg * 4096 + row * 4 + j];
            size_t yi = ((size_t)t * B_SZ + b) * H_SZ + row;
            float p = yio[yi];                       // pre (from GEMM), read once
            float n = tanhf(p + dot);
            float z = g_z[row];
            float hnew = fmaf(z, hold - n, n);       // z*h + (1-z)*n
            yio[yi] = hnew;                          // y_t, in place
            g_h[(t + 1) & 1][row * B_SZ + b] = hnew;
            if (t == T_STEPS - 1)
                hn[(size_t)b * H_SZ + row] = hnew;
        }

        // grid barrier (monotonic counter, reset by prep each launch)
        __threadfence();
        __syncthreads();
        target += G_CTAS;
        if (tid == 0) {
            atomicAdd(&g_bar, 1u);
            while (*((volatile unsigned*)&g_bar) < target) { }
        }
        __syncthreads();
    }
}

// ---------------- launch ----------------
extern "C" void kernel_launch(void* const* d_in, const int* in_sizes, int n_in,
                              void* d_out, int out_size)
{
    (void)in_sizes; (void)n_in; (void)out_size;
    const float* x   = (const float*)d_in[0];
    const float* h0  = (const float*)d_in[1];
    const float* wih = (const float*)d_in[2];
    const float* whh = (const float*)d_in[3];
    const float* bz  = (const float*)d_in[4];
    const float* bn  = (const float*)d_in[5];
    const float* brf = (const float*)d_in[6];

    float* y  = (float*)d_out;
    float* hn = y + (size_t)T_STEPS * B_SZ * H_SZ;

    prep_kernel<<<H_SZ + 1, 256>>>(whh, brf, bz, h0);

    dim3 g(H_SZ / 128, (T_STEPS * B_SZ) / 128);
    gemm_pre_kernel<<<g, 256>>>(x, wih, bn, y);

    cudaFuncSetAttribute(recur_kernel,
                         cudaFuncAttributeMaxDynamicSharedMemorySize, 98304);
    recur_kernel<<<G_CTAS, 256, 98304>>>(y, hn);
}

// round 2
// speedup vs baseline: 1.1199x; 1.1199x over previous
#include <cuda_runtime.h>
#include <math.h>

#define T_STEPS 2048
#define B_SZ 16
#define H_SZ 1024
#define I_SZ 1024
#define G_CTAS 128

typedef unsigned long long ull;

// ---------------- device scratch ----------------
__device__ float    g_Wr[H_SZ * H_SZ];
__device__ float    g_z[H_SZ];
__device__ float    g_h[2][H_SZ * B_SZ];   // [k][b]
__device__ unsigned g_bar;

// ---------------- f32x2 helpers (Blackwell packed fp32) ----------------
__device__ __forceinline__ ull pack2(float x, float y) {
    ull r; asm("mov.b64 %0, {%1,%2};" : "=l"(r) : "f"(x), "f"(y)); return r;
}
__device__ __forceinline__ float2 unpack2(ull v) {
    float2 r; asm("mov.b64 {%0,%1}, %2;" : "=f"(r.x), "=f"(r.y) : "l"(v)); return r;
}
__device__ __forceinline__ void ffma2(ull& d, ull a, ull b) {
    asm("fma.rn.f32x2 %0, %1, %2, %0;" : "+l"(d) : "l"(a), "l"(b));
}
__device__ __forceinline__ ull addp(ull a, ull b) {
    ull r; asm("add.rn.f32x2 %0, %1, %2;" : "=l"(r) : "l"(a), "l"(b)); return r;
}

// ---------------- prep ----------------
__global__ void __launch_bounds__(256) prep_kernel(
    const float* __restrict__ Whh, const float* __restrict__ brf,
    const float* __restrict__ bz,  const float* __restrict__ h0)
{
    int blk = blockIdx.x;
    if (blk < H_SZ) {
        int row = blk;
        float r = 1.0f / (1.0f + expf(-brf[row]));
        const float* src = Whh + (size_t)(2 * H_SZ + row) * H_SZ;
        for (int k = threadIdx.x; k < H_SZ; k += 256)
            g_Wr[row * H_SZ + k] = (k == row) ? 0.0f : r * src[k];
        if (threadIdx.x == 0)
            g_z[row] = 1.0f / (1.0f + expf(-bz[row]));
    } else {
        for (int i = threadIdx.x; i < H_SZ * B_SZ; i += 256) {
            int k = i >> 4, b = i & 15;
            g_h[0][i] = h0[(size_t)b * H_SZ + k];
        }
        if (threadIdx.x == 0) g_bar = 0u;
    }
}

// ---------------- GEMM: pre = x @ W_in^T + bias_n (into y region) ----------------
// 128x128 tile, BK=8, 256 threads, 8x8/thread, double-buffered smem, f32x2 FMA.
__global__ void __launch_bounds__(256) gemm_pre_kernel(
    const float* __restrict__ X, const float* __restrict__ Wih,
    const float* __restrict__ bn, float* __restrict__ out)
{
    __shared__ float As[2][8][128];
    __shared__ float Bs[2][8][128];
    const float* Wn = Wih + (size_t)2 * H_SZ * I_SZ;

    int m0 = blockIdx.y * 128;
    int n0 = blockIdx.x * 128;
    int t  = threadIdx.x;
    int ty = t >> 4, tx = t & 15;
    int lrow = t >> 1;
    int lk   = (t & 1) * 4;

    ull accp[8][4];
#pragma unroll
    for (int i = 0; i < 8; i++)
#pragma unroll
        for (int j = 0; j < 4; j++) accp[i][j] = 0ull;

    const float* Aptr = X  + (size_t)(m0 + lrow) * I_SZ + lk;
    const float* Bptr = Wn + (size_t)(n0 + lrow) * I_SZ + lk;

    {
        float4 a = *(const float4*)Aptr;
        float4 b = *(const float4*)Bptr;
        As[0][lk + 0][lrow] = a.x; As[0][lk + 1][lrow] = a.y;
        As[0][lk + 2][lrow] = a.z; As[0][lk + 3][lrow] = a.w;
        Bs[0][lk + 0][lrow] = b.x; Bs[0][lk + 1][lrow] = b.y;
        Bs[0][lk + 2][lrow] = b.z; Bs[0][lk + 3][lrow] = b.w;
    }
    __syncthreads();

    int buf = 0;
#pragma unroll 2
    for (int k0 = 8; k0 <= I_SZ; k0 += 8) {
        float4 a, b;
        bool more = (k0 < I_SZ);
        if (more) {
            a = *(const float4*)(Aptr + k0);
            b = *(const float4*)(Bptr + k0);
        }
#pragma unroll
        for (int kk = 0; kk < 8; kk++) {
            const float4* ap4 = (const float4*)&As[buf][kk][ty * 8];
            float4 a0 = ap4[0], a1 = ap4[1];
            const ull* bp = (const ull*)&Bs[buf][kk][tx * 8];
            ull rb0 = bp[0], rb1 = bp[1], rb2 = bp[2], rb3 = bp[3];
            float ra[8] = {a0.x, a0.y, a0.z, a0.w, a1.x, a1.y, a1.z, a1.w};
#pragma unroll
            for (int i = 0; i < 8; i++) {
                ull av = pack2(ra[i], ra[i]);
                ffma2(accp[i][0], av, rb0);
                ffma2(accp[i][1], av, rb1);
                ffma2(accp[i][2], av, rb2);
                ffma2(accp[i][3], av, rb3);
            }
        }
        if (more) {
            int nb = buf ^ 1;
            As[nb][lk + 0][lrow] = a.x; As[nb][lk + 1][lrow] = a.y;
            As[nb][lk + 2][lrow] = a.z; As[nb][lk + 3][lrow] = a.w;
            Bs[nb][lk + 0][lrow] = b.x; Bs[nb][lk + 1][lrow] = b.y;
            Bs[nb][lk + 2][lrow] = b.z; Bs[nb][lk + 3][lrow] = b.w;
        }
        __syncthreads();
        buf ^= 1;
    }

    float bj[8];
#pragma unroll
    for (int j = 0; j < 8; j++) bj[j] = bn[n0 + tx * 8 + j];

#pragma unroll
    for (int i = 0; i < 8; i++) {
        float o[8];
#pragma unroll
        for (int jp = 0; jp < 4; jp++) {
            float2 u = unpack2(accp[i][jp]);
            o[jp * 2 + 0] = u.x + bj[jp * 2 + 0];
            o[jp * 2 + 1] = u.y + bj[jp * 2 + 1];
        }
        size_t off = (size_t)(m0 + ty * 8 + i) * H_SZ + n0 + tx * 8;
        *(float4*)(out + off)     = make_float4(o[0], o[1], o[2], o[3]);
        *(float4*)(out + off + 4) = make_float4(o[4], o[5], o[6], o[7]);
    }
}

// ---------------- persistent recurrence ----------------
__global__ void __launch_bounds__(256) recur_kernel(
    float* __restrict__ yio, float* __restrict__ hn)
{
    extern __shared__ float smem[];
    float* W_s = smem;          // 8192 floats (32KB)
    float* h_s = smem + 8192;   // 16384 floats (64KB)

    int c    = blockIdx.x;
    int tid  = threadIdx.x;
    int warp = tid >> 5, lane = tid & 31;
    int rg = warp & 1, bg = warp >> 1;

    // one-time W slice load, transposed to [rg][k][row-in-4]
    for (int i = tid; i < 2048; i += 256) {
        int r  = i >> 8;
        int kq = i & 255;
        float4 w = *(const float4*)(g_Wr + (size_t)(c * 8 + r) * H_SZ + kq * 4);
        int rgL = r >> 2, rL = r & 3;
        W_s[rgL * 4096 + (kq * 4 + 0) * 4 + rL] = w.x;
        W_s[rgL * 4096 + (kq * 4 + 1) * 4 + rL] = w.y;
        W_s[rgL * 4096 + (kq * 4 + 2) * 4 + rL] = w.z;
        W_s[rgL * 4096 + (kq * 4 + 3) * 4 + rL] = w.w;
    }

    // per-lane constants (lanes 0..15 are the "active" output lanes)
    int li = lane >> 2, lj = lane & 3;
    int row = c * 8 + rg * 4 + li;
    int b   = bg * 4 + lj;
    bool act = (lane < 16);
    float z = 0.0f;
    size_t yi = 0;
    if (act) {
        z  = g_z[row];
        yi = (size_t)b * H_SZ + row;
    }
    __syncthreads();

    const float* Wb = &W_s[rg * 4096];
    const float* Hb = &h_s[bg * 4096];

    unsigned target = 0;
    for (int t = 0; t < T_STEPS; ++t) {
        // prefetch pre (DRAM latency hidden under h load + compute)
        float p = 0.0f;
        if (act) p = __ldcg(yio + yi);

        const float4* hp = (const float4*)(g_h[t & 1]);
        float4 r0[8], r1[8];
#pragma unroll
        for (int j = 0; j < 8; j++) r0[j] = __ldcg(hp + tid + j * 256);
#pragma unroll
        for (int j = 0; j < 8; j++) {
            int i = tid + j * 256;
            *(float4*)&h_s[(i & 3) * 4096 + (i >> 2) * 4] = r0[j];
        }
        __syncthreads();

        // issue second-half loads before computing on first half
#pragma unroll
        for (int j = 0; j < 8; j++) r1[j] = __ldcg(hp + 2048 + tid + j * 256);

        ull acc[4][2];
#pragma unroll
        for (int i = 0; i < 4; i++) { acc[i][0] = 0ull; acc[i][1] = 0ull; }

#pragma unroll
        for (int it = 0; it < 16; ++it) {
            int k = lane + (it << 5);
            float4 w = *(const float4*)(Wb + k * 4);
            ulonglong2 hq = *(const ulonglong2*)(Hb + k * 4);
            ull w0 = pack2(w.x, w.x), w1 = pack2(w.y, w.y);
            ull w2 = pack2(w.z, w.z), w3 = pack2(w.w, w.w);
            ffma2(acc[0][0], w0, hq.x); ffma2(acc[0][1], w0, hq.y);
            ffma2(acc[1][0], w1, hq.x); ffma2(acc[1][1], w1, hq.y);
            ffma2(acc[2][0], w2, hq.x); ffma2(acc[2][1], w2, hq.y);
            ffma2(acc[3][0], w3, hq.x); ffma2(acc[3][1], w3, hq.y);
        }

#pragma unroll
        for (int j = 0; j < 8; j++) {
            int i = 2048 + tid + j * 256;
            *(float4*)&h_s[(i & 3) * 4096 + (i >> 2) * 4] = r1[j];
        }
        __syncthreads();

#pragma unroll
        for (int it = 16; it < 32; ++it) {
            int k = lane + (it << 5);
            float4 w = *(const float4*)(Wb + k * 4);
            ulonglong2 hq = *(const ulonglong2*)(Hb + k * 4);
            ull w0 = pack2(w.x, w.x), w1 = pack2(w.y, w.y);
            ull w2 = pack2(w.z, w.z), w3 = pack2(w.w, w.w);
            ffma2(acc[0][0], w0, hq.x); ffma2(acc[0][1], w0, hq.y);
            ffma2(acc[1][0], w1, hq.x); ffma2(acc[1][1], w1, hq.y);
            ffma2(acc[2][0], w2, hq.x); ffma2(acc[2][1], w2, hq.y);
            ffma2(acc[3][0], w3, hq.x); ffma2(acc[3][1], w3, hq.y);
        }

        // packed butterfly reduction across the 32 K-segments
#pragma unroll
        for (int off = 16; off > 0; off >>= 1) {
#pragma unroll
            for (int i = 0; i < 4; i++) {
                acc[i][0] = addp(acc[i][0], __shfl_xor_sync(0xffffffffu, acc[i][0], off));
                acc[i][1] = addp(acc[i][1], __shfl_xor_sync(0xffffffffu, acc[i][1], off));
            }
        }

        if (act) {
            float dot = 0.0f;
#pragma unroll
            for (int ii = 0; ii < 4; ii++) {
#pragma unroll
                for (int jp = 0; jp < 2; jp++) {
                    float2 u = unpack2(acc[ii][jp]);
                    if (lane == ii * 4 + jp * 2)     dot = u.x;
                    if (lane == ii * 4 + jp * 2 + 1) dot = u.y;
                }
            }
            float hold = h_s[bg * 4096 + row * 4 + lj];
            float n = tanhf(p + dot);
            float hnew = fmaf(z, hold - n, n);
            __stcg(yio + yi, hnew);
            g_h[(t + 1) & 1][row * B_SZ + b] = hnew;
            if (t == T_STEPS - 1)
                hn[(size_t)b * H_SZ + row] = hnew;
            yi += (size_t)B_SZ * H_SZ;
        }

        // grid barrier
        __threadfence();
        __syncthreads();
        target += G_CTAS;
        if (tid == 0) {
            atomicAdd(&g_bar, 1u);
            while (*((volatile unsigned*)&g_bar) < target) { }
        }
        __syncthreads();
    }
}

// ---------------- launch ----------------
extern "C" void kernel_launch(void* const* d_in, const int* in_sizes, int n_in,
                              void* d_out, int out_size)
{
    (void)in_sizes; (void)n_in; (void)out_size;
    const float* x   = (const float*)d_in[0];
    const float* h0  = (const float*)d_in[1];
    const float* wih = (const float*)d_in[2];
    const float* whh = (const float*)d_in[3];
    const float* bz  = (const float*)d_in[4];
    const float* bn  = (const float*)d_in[5];
    const float* brf = (const float*)d_in[6];

    float* y  = (float*)d_out;
    float* hn = y + (size_t)T_STEPS * B_SZ * H_SZ;

    prep_kernel<<<H_SZ + 1, 256>>>(whh, brf, bz, h0);

    dim3 g(H_SZ / 128, (T_STEPS * B_SZ) / 128);
    gemm_pre_kernel<<<g, 256>>>(x, wih, bn, y);

    cudaFuncSetAttribute(recur_kernel,
                         cudaFuncAttributeMaxDynamicSharedMemorySize, 98304);
    recur_kernel<<<G_CTAS, 256, 98304>>>(y, hn);
}

// round 3
// speedup vs baseline: 1.1872x; 1.0601x over previous
#include <cuda_runtime.h>
#include <math.h>

#define T_STEPS 2048
#define B_SZ 16
#define H_SZ 1024
#define I_SZ 1024
#define G_CTAS 128

typedef unsigned long long ull;

// ---------------- device scratch ----------------
__device__ float    g_Wr[H_SZ * H_SZ];
__device__ float    g_z[H_SZ];
__device__ float    g_h[2][H_SZ * B_SZ];          // [k][b]
__device__ unsigned g_flags[G_CTAS * 32];          // 1 flag per CTA, 128B stride

// ---------------- f32x2 helpers ----------------
__device__ __forceinline__ ull pack2(float x, float y) {
    ull r; asm("mov.b64 %0, {%1,%2};" : "=l"(r) : "f"(x), "f"(y)); return r;
}
__device__ __forceinline__ float2 unpack2(ull v) {
    float2 r; asm("mov.b64 {%0,%1}, %2;" : "=f"(r.x), "=f"(r.y) : "l"(v)); return r;
}
__device__ __forceinline__ void ffma2(ull& d, ull a, ull b) {
    asm("fma.rn.f32x2 %0, %1, %2, %0;" : "+l"(d) : "l"(a), "l"(b));
}
__device__ __forceinline__ ull addp(ull a, ull b) {
    ull r; asm("add.rn.f32x2 %0, %1, %2;" : "=l"(r) : "l"(a), "l"(b)); return r;
}

// ---------------- prep ----------------
__global__ void __launch_bounds__(256) prep_kernel(
    const float* __restrict__ Whh, const float* __restrict__ brf,
    const float* __restrict__ bz,  const float* __restrict__ h0)
{
    int blk = blockIdx.x;
    if (blk < H_SZ) {
        int row = blk;
        float r = 1.0f / (1.0f + expf(-brf[row]));
        const float* src = Whh + (size_t)(2 * H_SZ + row) * H_SZ;
        for (int k = threadIdx.x; k < H_SZ; k += 256)
            g_Wr[row * H_SZ + k] = (k == row) ? 0.0f : r * src[k];
        if (threadIdx.x == 0)
            g_z[row] = 1.0f / (1.0f + expf(-bz[row]));
    } else {
        for (int i = threadIdx.x; i < H_SZ * B_SZ; i += 256) {
            int k = i >> 4, b = i & 15;
            g_h[0][i] = h0[(size_t)b * H_SZ + k];
        }
        for (int i = threadIdx.x; i < G_CTAS; i += 256)
            g_flags[i * 32] = 0u;
    }
}

__global__ void noop_kernel() {}

// ---------------- GEMM: pre = x @ W_in^T + bias_n (into y region) ----------------
__global__ void __launch_bounds__(256) gemm_pre_kernel(
    const float* __restrict__ X, const float* __restrict__ Wih,
    const float* __restrict__ bn, float* __restrict__ out)
{
    __shared__ float As[2][8][128];
    __shared__ float Bs[2][8][128];
    const float* Wn = Wih + (size_t)2 * H_SZ * I_SZ;

    int m0 = blockIdx.y * 128;
    int n0 = blockIdx.x * 128;
    int t  = threadIdx.x;
    int ty = t >> 4, tx = t & 15;
    int lrow = t >> 1;
    int lk   = (t & 1) * 4;

    ull accp[8][4];
#pragma unroll
    for (int i = 0; i < 8; i++)
#pragma unroll
        for (int j = 0; j < 4; j++) accp[i][j] = 0ull;

    const float* Aptr = X  + (size_t)(m0 + lrow) * I_SZ + lk;
    const float* Bptr = Wn + (size_t)(n0 + lrow) * I_SZ + lk;

    {
        float4 a = *(const float4*)Aptr;
        float4 b = *(const float4*)Bptr;
        As[0][lk + 0][lrow] = a.x; As[0][lk + 1][lrow] = a.y;
        As[0][lk + 2][lrow] = a.z; As[0][lk + 3][lrow] = a.w;
        Bs[0][lk + 0][lrow] = b.x; Bs[0][lk + 1][lrow] = b.y;
        Bs[0][lk + 2][lrow] = b.z; Bs[0][lk + 3][lrow] = b.w;
    }
    __syncthreads();

    int buf = 0;
#pragma unroll 2
    for (int k0 = 8; k0 <= I_SZ; k0 += 8) {
        float4 a, b;
        bool more = (k0 < I_SZ);
        if (more) {
            a = *(const float4*)(Aptr + k0);
            b = *(const float4*)(Bptr + k0);
        }
#pragma unroll
        for (int kk = 0; kk < 8; kk++) {
            const float4* ap4 = (const float4*)&As[buf][kk][ty * 8];
            float4 a0 = ap4[0], a1 = ap4[1];
            const ull* bp = (const ull*)&Bs[buf][kk][tx * 8];
            ull rb0 = bp[0], rb1 = bp[1], rb2 = bp[2], rb3 = bp[3];
            float ra[8] = {a0.x, a0.y, a0.z, a0.w, a1.x, a1.y, a1.z, a1.w};
#pragma unroll
            for (int i = 0; i < 8; i++) {
                ull av = pack2(ra[i], ra[i]);
                ffma2(accp[i][0], av, rb0);
                ffma2(accp[i][1], av, rb1);
                ffma2(accp[i][2], av, rb2);
                ffma2(accp[i][3], av, rb3);
            }
        }
        if (more) {
            int nb = buf ^ 1;
            As[nb][lk + 0][lrow] = a.x; As[nb][lk + 1][lrow] = a.y;
            As[nb][lk + 2][lrow] = a.z; As[nb][lk + 3][lrow] = a.w;
            Bs[nb][lk + 0][lrow] = b.x; Bs[nb][lk + 1][lrow] = b.y;
            Bs[nb][lk + 2][lrow] = b.z; Bs[nb][lk + 3][lrow] = b.w;
        }
        __syncthreads();
        buf ^= 1;
    }

    float bj[8];
#pragma unroll
    for (int j = 0; j < 8; j++) bj[j] = bn[n0 + tx * 8 + j];

#pragma unroll
    for (int i = 0; i < 8; i++) {
        float o[8];
#pragma unroll
        for (int jp = 0; jp < 4; jp++) {
            float2 u = unpack2(accp[i][jp]);
            o[jp * 2 + 0] = u.x + bj[jp * 2 + 0];
            o[jp * 2 + 1] = u.y + bj[jp * 2 + 1];
        }
        size_t off = (size_t)(m0 + ty * 8 + i) * H_SZ + n0 + tx * 8;
        *(float4*)(out + off)     = make_float4(o[0], o[1], o[2], o[3]);
        *(float4*)(out + off + 4) = make_float4(o[4], o[5], o[6], o[7]);
    }
}

// ---------------- persistent recurrence ----------------
__global__ void __launch_bounds__(256) recur_kernel(
    float* __restrict__ yio, float* __restrict__ hn)
{
    extern __shared__ float smem[];
    float* W_s = smem;          // 8192 floats (32KB)
    float* h_s = smem + 8192;   // 16384 floats (64KB)

    int c    = blockIdx.x;
    int tid  = threadIdx.x;
    int warp = tid >> 5, lane = tid & 31;
    int rg = warp & 1, bg = warp >> 1;

    // one-time W slice load, transposed to [rg][k][row-in-4]
    for (int i = tid; i < 2048; i += 256) {
        int r  = i >> 8;
        int kq = i & 255;
        float4 w = *(const float4*)(g_Wr + (size_t)(c * 8 + r) * H_SZ + kq * 4);
        int rgL = r >> 2, rL = r & 3;
        W_s[rgL * 4096 + (kq * 4 + 0) * 4 + rL] = w.x;
        W_s[rgL * 4096 + (kq * 4 + 1) * 4 + rL] = w.y;
        W_s[rgL * 4096 + (kq * 4 + 2) * 4 + rL] = w.z;
        W_s[rgL * 4096 + (kq * 4 + 3) * 4 + rL] = w.w;
    }

    int li = lane >> 2, lj = lane & 3;
    int row = c * 8 + rg * 4 + li;
    int b   = bg * 4 + lj;
    bool act = (lane < 16);
    float z = 0.0f;
    size_t yi = 0;
    if (act) {
        z  = g_z[row];
        yi = (size_t)b * H_SZ + row;
    }
    __syncthreads();

    const float* Wb = &W_s[rg * 4096];
    const float* Hb = &h_s[bg * 4096];
    unsigned* myflag  = &g_flags[c * 32];
    unsigned* pollflag = &g_flags[(tid & (G_CTAS - 1)) * 32];

    // prefetch pre for t=0
    float p = 0.0f;
    if (act) p = __ldcg(yio + yi);

    for (int t = 0; t < T_STEPS; ++t) {
        // ---- load h: issue all 16 LDGs up front (MLP=16) ----
        const float4* hp = (const float4*)(g_h[t & 1]);
        float4 r0[8], r1[8];
#pragma unroll
        for (int j = 0; j < 8; j++) r0[j] = __ldcg(hp + tid + j * 256);
#pragma unroll
        for (int j = 0; j < 8; j++) r1[j] = __ldcg(hp + 2048 + tid + j * 256);
#pragma unroll
        for (int j = 0; j < 8; j++) {
            int i = tid + j * 256;
            *(float4*)&h_s[(i & 3) * 4096 + (i >> 2) * 4] = r0[j];
        }
        __syncthreads();

        ull acc[4][2];
#pragma unroll
        for (int i = 0; i < 4; i++) { acc[i][0] = 0ull; acc[i][1] = 0ull; }

#pragma unroll
        for (int it = 0; it < 16; ++it) {
            int k = lane + (it << 5);
            float4 w = *(const float4*)(Wb + k * 4);
            ulonglong2 hq = *(const ulonglong2*)(Hb + k * 4);
            ull w0 = pack2(w.x, w.x), w1 = pack2(w.y, w.y);
            ull w2 = pack2(w.z, w.z), w3 = pack2(w.w, w.w);
            ffma2(acc[0][0], w0, hq.x); ffma2(acc[0][1], w0, hq.y);
            ffma2(acc[1][0], w1, hq.x); ffma2(acc[1][1], w1, hq.y);
            ffma2(acc[2][0], w2, hq.x); ffma2(acc[2][1], w2, hq.y);
            ffma2(acc[3][0], w3, hq.x); ffma2(acc[3][1], w3, hq.y);
        }

#pragma unroll
        for (int j = 0; j < 8; j++) {
            int i = 2048 + tid + j * 256;
            *(float4*)&h_s[(i & 3) * 4096 + (i >> 2) * 4] = r1[j];
        }
        __syncthreads();

#pragma unroll
        for (int it = 16; it < 32; ++it) {
            int k = lane + (it << 5);
            float4 w = *(const float4*)(Wb + k * 4);
            ulonglong2 hq = *(const ulonglong2*)(Hb + k * 4);
            ull w0 = pack2(w.x, w.x), w1 = pack2(w.y, w.y);
            ull w2 = pack2(w.z, w.z), w3 = pack2(w.w, w.w);
            ffma2(acc[0][0], w0, hq.x); ffma2(acc[0][1], w0, hq.y);
            ffma2(acc[1][0], w1, hq.x); ffma2(acc[1][1], w1, hq.y);
            ffma2(acc[2][0], w2, hq.x); ffma2(acc[2][1], w2, hq.y);
            ffma2(acc[3][0], w3, hq.x); ffma2(acc[3][1], w3, hq.y);
        }

        // packed butterfly reduction across 32 K-segments
#pragma unroll
        for (int off = 16; off > 0; off >>= 1) {
#pragma unroll
            for (int i = 0; i < 4; i++) {
                acc[i][0] = addp(acc[i][0], __shfl_xor_sync(0xffffffffu, acc[i][0], off));
                acc[i][1] = addp(acc[i][1], __shfl_xor_sync(0xffffffffu, acc[i][1], off));
            }
        }

        float hnew = 0.0f;
        if (act) {
            float dot = 0.0f;
#pragma unroll
            for (int ii = 0; ii < 4; ii++) {
#pragma unroll
                for (int jp = 0; jp < 2; jp++) {
                    float2 u = unpack2(acc[ii][jp]);
                    if (lane == ii * 4 + jp * 2)     dot = u.x;
                    if (lane == ii * 4 + jp * 2 + 1) dot = u.y;
                }
            }
            float hold = h_s[bg * 4096 + row * 4 + lj];
            float n = tanhf(p + dot);
            hnew = fmaf(z, hold - n, n);
            g_h[(t + 1) & 1][row * B_SZ + b] = hnew;   // publish h FIRST
        }

        // all h stores in this CTA done -> arrive (release)
        __syncthreads();
        if (t < T_STEPS - 1) {
            if (tid == 0)
                asm volatile("red.release.gpu.global.add.u32 [%0], %1;"
                             :: "l"(myflag), "r"(1u) : "memory");
        }

        // off-critical-path work: y store, next-y prefetch, final hn
        if (act) {
            __stcg(yio + yi, hnew);
            if (t == T_STEPS - 1)
                hn[(size_t)b * H_SZ + row] = hnew;
            yi += (size_t)B_SZ * H_SZ;
            if (t < T_STEPS - 1)
                p = __ldcg(yio + yi);
        }

        // wait: 128 threads poll 128 flags in parallel (acquire)
        if (t < T_STEPS - 1) {
            if (tid < G_CTAS) {
                unsigned target = (unsigned)(t + 1), v;
                do {
                    asm volatile("ld.acquire.gpu.global.u32 %0, [%1];"
                                 : "=r"(v) : "l"(pollflag) : "memory");
                } while (v < target);
            }
            __syncthreads();
        }
    }
}

// ---------------- launch ----------------
extern "C" void kernel_launch(void* const* d_in, const int* in_sizes, int n_in,
                              void* d_out, int out_size)
{
    (void)in_sizes; (void)n_in; (void)out_size;
    const float* x   = (const float*)d_in[0];
    const float* h0  = (const float*)d_in[1];
    const float* wih = (const float*)d_in[2];
    const float* whh = (const float*)d_in[3];
    const float* bz  = (const float*)d_in[4];
    const float* bn  = (const float*)d_in[5];
    const float* brf = (const float*)d_in[6];

    float* y  = (float*)d_out;
    float* hn = y + (size_t)T_STEPS * B_SZ * H_SZ;

    prep_kernel<<<H_SZ + 1, 256>>>(whh, brf, bz, h0);

    dim3 g(H_SZ / 128, (T_STEPS * B_SZ) / 128);
    gemm_pre_kernel<<<g, 256>>>(x, wih, bn, y);

    // pad launch count so ncu's "-s 5 -c 1" window lands on recur_kernel
    noop_kernel<<<1, 32>>>();
    noop_kernel<<<1, 32>>>();
    noop_kernel<<<1, 32>>>();

    cudaFuncSetAttribute(recur_kernel,
                         cudaFuncAttributeMaxDynamicSharedMemorySize, 98304);
    recur_kernel<<<G_CTAS, 256, 98304>>>(y, hn);
}

// round 4
// speedup vs baseline: 1.3573x; 1.1433x over previous
#include <cuda_runtime.h>
#include <math.h>

#define T_STEPS 2048
#define B_SZ 16
#define H_SZ 1024
#define I_SZ 1024
#define G_CTAS 128

typedef unsigned long long ull;

// ---------------- device scratch ----------------
__device__ float    g_Wr[H_SZ * H_SZ];
__device__ float    g_z[H_SZ];
// h double buffer in the SMEM-friendly layout: [bg(4)][k(1024)][b4(4)]
__device__ float    g_h[2][H_SZ * B_SZ];
__device__ unsigned g_flags[G_CTAS * 32];          // 1 flag per CTA, 128B stride

// ---------------- f32x2 helpers ----------------
__device__ __forceinline__ ull pack2(float x, float y) {
    ull r; asm("mov.b64 %0, {%1,%2};" : "=l"(r) : "f"(x), "f"(y)); return r;
}
__device__ __forceinline__ float2 unpack2(ull v) {
    float2 r; asm("mov.b64 {%0,%1}, %2;" : "=f"(r.x), "=f"(r.y) : "l"(v)); return r;
}
__device__ __forceinline__ void ffma2(ull& d, ull a, ull b) {
    asm("fma.rn.f32x2 %0, %1, %2, %0;" : "+l"(d) : "l"(a), "l"(b));
}
__device__ __forceinline__ ull addp(ull a, ull b) {
    ull r; asm("add.rn.f32x2 %0, %1, %2;" : "=l"(r) : "l"(a), "l"(b)); return r;
}

// ---------------- prep ----------------
__global__ void __launch_bounds__(256) prep_kernel(
    const float* __restrict__ Whh, const float* __restrict__ brf,
    const float* __restrict__ bz,  const float* __restrict__ h0)
{
    int blk = blockIdx.x;
    if (blk < H_SZ) {
        int row = blk;
        float r = 1.0f / (1.0f + expf(-brf[row]));
        const float* src = Whh + (size_t)(2 * H_SZ + row) * H_SZ;
        for (int k = threadIdx.x; k < H_SZ; k += 256)
            g_Wr[row * H_SZ + k] = (k == row) ? 0.0f : r * src[k];
        if (threadIdx.x == 0)
            g_z[row] = 1.0f / (1.0f + expf(-bz[row]));
    } else {
        // h0: [b][k]  ->  g_h[0] layout [bg][k][b4]
        for (int i = threadIdx.x; i < H_SZ * B_SZ; i += 256) {
            int bg = i >> 12;
            int k  = (i >> 2) & (H_SZ - 1);
            int b4 = i & 3;
            g_h[0][i] = h0[(size_t)(bg * 4 + b4) * H_SZ + k];
        }
        for (int i = threadIdx.x; i < G_CTAS; i += 256)
            g_flags[i * 32] = 0u;
    }
}

__global__ void noop_kernel() {}

// ---------------- GEMM: pre = x @ W_in^T + bias_n (into y region) ----------------
__global__ void __launch_bounds__(256) gemm_pre_kernel(
    const float* __restrict__ X, const float* __restrict__ Wih,
    const float* __restrict__ bn, float* __restrict__ out)
{
    __shared__ float As[2][8][128];
    __shared__ float Bs[2][8][128];
    const float* Wn = Wih + (size_t)2 * H_SZ * I_SZ;

    int m0 = blockIdx.y * 128;
    int n0 = blockIdx.x * 128;
    int t  = threadIdx.x;
    int ty = t >> 4, tx = t & 15;
    int lrow = t >> 1;
    int lk   = (t & 1) * 4;

    ull accp[8][4];
#pragma unroll
    for (int i = 0; i < 8; i++)
#pragma unroll
        for (int j = 0; j < 4; j++) accp[i][j] = 0ull;

    const float* Aptr = X  + (size_t)(m0 + lrow) * I_SZ + lk;
    const float* Bptr = Wn + (size_t)(n0 + lrow) * I_SZ + lk;

    {
        float4 a = *(const float4*)Aptr;
        float4 b = *(const float4*)Bptr;
        As[0][lk + 0][lrow] = a.x; As[0][lk + 1][lrow] = a.y;
        As[0][lk + 2][lrow] = a.z; As[0][lk + 3][lrow] = a.w;
        Bs[0][lk + 0][lrow] = b.x; Bs[0][lk + 1][lrow] = b.y;
        Bs[0][lk + 2][lrow] = b.z; Bs[0][lk + 3][lrow] = b.w;
    }
    __syncthreads();

    int buf = 0;
#pragma unroll 2
    for (int k0 = 8; k0 <= I_SZ; k0 += 8) {
        float4 a, b;
        bool more = (k0 < I_SZ);
        if (more) {
            a = *(const float4*)(Aptr + k0);
            b = *(const float4*)(Bptr + k0);
        }
#pragma unroll
        for (int kk = 0; kk < 8; kk++) {
            const float4* ap4 = (const float4*)&As[buf][kk][ty * 8];
            float4 a0 = ap4[0], a1 = ap4[1];
            const ull* bp = (const ull*)&Bs[buf][kk][tx * 8];
            ull rb0 = bp[0], rb1 = bp[1], rb2 = bp[2], rb3 = bp[3];
            float ra[8] = {a0.x, a0.y, a0.z, a0.w, a1.x, a1.y, a1.z, a1.w};
#pragma unroll
            for (int i = 0; i < 8; i++) {
                ull av = pack2(ra[i], ra[i]);
                ffma2(accp[i][0], av, rb0);
                ffma2(accp[i][1], av, rb1);
                ffma2(accp[i][2], av, rb2);
                ffma2(accp[i][3], av, rb3);
            }
        }
        if (more) {
            int nb = buf ^ 1;
            As[nb][lk + 0][lrow] = a.x; As[nb][lk + 1][lrow] = a.y;
            As[nb][lk + 2][lrow] = a.z; As[nb][lk + 3][lrow] = a.w;
            Bs[nb][lk + 0][lrow] = b.x; Bs[nb][lk + 1][lrow] = b.y;
            Bs[nb][lk + 2][lrow] = b.z; Bs[nb][lk + 3][lrow] = b.w;
        }
        __syncthreads();
        buf ^= 1;
    }

    float bj[8];
#pragma unroll
    for (int j = 0; j < 8; j++) bj[j] = bn[n0 + tx * 8 + j];

#pragma unroll
    for (int i = 0; i < 8; i++) {
        float o[8];
#pragma unroll
        for (int jp = 0; jp < 4; jp++) {
            float2 u = unpack2(accp[i][jp]);
            o[jp * 2 + 0] = u.x + bj[jp * 2 + 0];
            o[jp * 2 + 1] = u.y + bj[jp * 2 + 1];
        }
        size_t off = (size_t)(m0 + ty * 8 + i) * H_SZ + n0 + tx * 8;
        *(float4*)(out + off)     = make_float4(o[0], o[1], o[2], o[3]);
        *(float4*)(out + off + 4) = make_float4(o[4], o[5], o[6], o[7]);
    }
}

// ---------------- persistent recurrence ----------------
__global__ void __launch_bounds__(256) recur_kernel(
    float* __restrict__ yio, float* __restrict__ hn)
{
    extern __shared__ float smem[];
    float* W_s = smem;          // 8192 floats (32KB), [rg][k][r4]
    float* h_s = smem + 8192;   // 16384 floats (64KB), [bg][k][b4]

    int c    = blockIdx.x;
    int tid  = threadIdx.x;
    int warp = tid >> 5, lane = tid & 31;
    int rg = warp & 1, bg = warp >> 1;

    // one-time W slice load, transposed to [rg][k][row-in-4]
    for (int i = tid; i < 2048; i += 256) {
        int r  = i >> 8;
        int kq = i & 255;
        float4 w = *(const float4*)(g_Wr + (size_t)(c * 8 + r) * H_SZ + kq * 4);
        int rgL = r >> 2, rL = r & 3;
        W_s[rgL * 4096 + (kq * 4 + 0) * 4 + rL] = w.x;
        W_s[rgL * 4096 + (kq * 4 + 1) * 4 + rL] = w.y;
        W_s[rgL * 4096 + (kq * 4 + 2) * 4 + rL] = w.z;
        W_s[rgL * 4096 + (kq * 4 + 3) * 4 + rL] = w.w;
    }

    int li = lane >> 2, lj = lane & 3;
    int row = c * 8 + rg * 4 + li;
    int b   = bg * 4 + lj;
    bool act = (lane < 16);
    float z = 0.0f;
    size_t yi = 0;
    if (act) {
        z  = g_z[row];
        yi = (size_t)b * H_SZ + row;
    }
    __syncthreads();

    const float* Wb = &W_s[rg * 4096];
    const float* Hb = &h_s[bg * 4096];
    unsigned* myflag   = &g_flags[c * 32];
    unsigned* pollflag = &g_flags[(tid & (G_CTAS - 1)) * 32];

    // prefetch pre for t=0
    float p = 0.0f;
    if (act) p = __ldcg(yio + yi);

    for (int t = 0; t < T_STEPS; ++t) {
        // ---- load h: g_h layout == h_s layout, linear conflict-free copy.
        // halves split by k: idxA covers k<512 for all bg, idxB covers k>=512.
        const float4* hp = (const float4*)(g_h[t & 1]);
        float4 r0[8], r1[8];
#pragma unroll
        for (int j = 0; j < 8; j++) {
            int idx = (j >> 1) * 1024 + (j & 1) * 256 + tid;
            r0[j] = __ldcg(hp + idx);
        }
#pragma unroll
        for (int j = 0; j < 8; j++) {
            int idx = (j >> 1) * 1024 + 512 + (j & 1) * 256 + tid;
            r1[j] = __ldcg(hp + idx);
        }
#pragma unroll
        for (int j = 0; j < 8; j++) {
            int idx = (j >> 1) * 1024 + (j & 1) * 256 + tid;
            *(float4*)&h_s[idx * 4] = r0[j];
        }
        __syncthreads();

        ull acc[4][2];
#pragma unroll
        for (int i = 0; i < 4; i++) { acc[i][0] = 0ull; acc[i][1] = 0ull; }

#pragma unroll
        for (int it = 0; it < 16; ++it) {
            int k = lane + (it << 5);
            float4 w = *(const float4*)(Wb + k * 4);
            ulonglong2 hq = *(const ulonglong2*)(Hb + k * 4);
            ull w0 = pack2(w.x, w.x), w1 = pack2(w.y, w.y);
            ull w2 = pack2(w.z, w.z), w3 = pack2(w.w, w.w);
            ffma2(acc[0][0], w0, hq.x); ffma2(acc[0][1], w0, hq.y);
            ffma2(acc[1][0], w1, hq.x); ffma2(acc[1][1], w1, hq.y);
            ffma2(acc[2][0], w2, hq.x); ffma2(acc[2][1], w2, hq.y);
            ffma2(acc[3][0], w3, hq.x); ffma2(acc[3][1], w3, hq.y);
        }

#pragma unroll
        for (int j = 0; j < 8; j++) {
            int idx = (j >> 1) * 1024 + 512 + (j & 1) * 256 + tid;
            *(float4*)&h_s[idx * 4] = r1[j];
        }
        __syncthreads();

#pragma unroll
        for (int it = 16; it < 32; ++it) {
            int k = lane + (it << 5);
            float4 w = *(const float4*)(Wb + k * 4);
            ulonglong2 hq = *(const ulonglong2*)(Hb + k * 4);
            ull w0 = pack2(w.x, w.x), w1 = pack2(w.y, w.y);
            ull w2 = pack2(w.z, w.z), w3 = pack2(w.w, w.w);
            ffma2(acc[0][0], w0, hq.x); ffma2(acc[0][1], w0, hq.y);
            ffma2(acc[1][0], w1, hq.x); ffma2(acc[1][1], w1, hq.y);
            ffma2(acc[2][0], w2, hq.x); ffma2(acc[2][1], w2, hq.y);
            ffma2(acc[3][0], w3, hq.x); ffma2(acc[3][1], w3, hq.y);
        }

        // packed butterfly reduction across 32 K-segments
#pragma unroll
        for (int off = 16; off > 0; off >>= 1) {
#pragma unroll
            for (int i = 0; i < 4; i++) {
                acc[i][0] = addp(acc[i][0], __shfl_xor_sync(0xffffffffu, acc[i][0], off));
                acc[i][1] = addp(acc[i][1], __shfl_xor_sync(0xffffffffu, acc[i][1], off));
            }
        }

        float hnew = 0.0f;
        if (act) {
            float dot = 0.0f;
#pragma unroll
            for (int ii = 0; ii < 4; ii++) {
#pragma unroll
                for (int jp = 0; jp < 2; jp++) {
                    float2 u = unpack2(acc[ii][jp]);
                    if (lane == ii * 4 + jp * 2)     dot = u.x;
                    if (lane == ii * 4 + jp * 2 + 1) dot = u.y;
                }
            }
            float hold = h_s[bg * 4096 + row * 4 + lj];
            float n = tanhf(p + dot);
            hnew = fmaf(z, hold - n, n);
            // publish h in [bg][k][b4] layout
            g_h[(t + 1) & 1][bg * 4096 + row * 4 + lj] = hnew;
        }

        // all h stores in this CTA done -> arrive (release)
        __syncthreads();
        if (t < T_STEPS - 1) {
            if (tid == 0)
                asm volatile("red.release.gpu.global.add.u32 [%0], %1;"
                             :: "l"(myflag), "r"(1u) : "memory");
        }

        // off-critical-path work
        if (act) {
            __stcg(yio + yi, hnew);
            if (t == T_STEPS - 1)
                hn[(size_t)b * H_SZ + row] = hnew;
            yi += (size_t)B_SZ * H_SZ;
            if (t < T_STEPS - 1)
                p = __ldcg(yio + yi);
        }

        // wait: 128 threads poll 128 distinct flag lines (acquire)
        if (t < T_STEPS - 1) {
            if (tid < G_CTAS) {
                unsigned target = (unsigned)(t + 1), v;
                do {
                    asm volatile("ld.acquire.gpu.global.u32 %0, [%1];"
                                 : "=r"(v) : "l"(pollflag) : "memory");
                } while (v < target);
            }
            __syncthreads();
        }
    }
}

// ---------------- launch ----------------
extern "C" void kernel_launch(void* const* d_in, const int* in_sizes, int n_in,
                              void* d_out, int out_size)
{
    (void)in_sizes; (void)n_in; (void)out_size;
    const float* x   = (const float*)d_in[0];
    const float* h0  = (const float*)d_in[1];
    const float* wih = (const float*)d_in[2];
    const float* whh = (const float*)d_in[3];
    const float* bz  = (const float*)d_in[4];
    const float* bn  = (const float*)d_in[5];
    const float* brf = (const float*)d_in[6];

    float* y  = (float*)d_out;
    float* hn = y + (size_t)T_STEPS * B_SZ * H_SZ;

    prep_kernel<<<H_SZ + 1, 256>>>(whh, brf, bz, h0);

    dim3 g(H_SZ / 128, (T_STEPS * B_SZ) / 128);
    gemm_pre_kernel<<<g, 256>>>(x, wih, bn, y);

    // pad launch count so ncu's "-s 5 -c 1" window lands on recur_kernel
    noop_kernel<<<1, 32>>>();
    noop_kernel<<<1, 32>>>();
    noop_kernel<<<1, 32>>>();

    cudaFuncSetAttribute(recur_kernel,
                         cudaFuncAttributeMaxDynamicSharedMemorySize, 98304);
    recur_kernel<<<G_CTAS, 256, 98304>>>(y, hn);
}